// round 1
// baseline (speedup 1.0000x reference)
#include <cuda_runtime.h>
#include <cstdint>

// ---------------- problem dims ----------------
#define BB 128
#define TT 256
#define ND 128
#define KD 128
#define VD 128
#define FD 2048
#define OD 4096   // ODIM*NDIM

// ---------------- device scratch (no allocations allowed) ----------------
__device__ float g_q[(size_t)BB * TT * KD];
__device__ float g_k[(size_t)BB * TT * KD];
__device__ float g_v[(size_t)BB * TT * VD];
__device__ float g_r[(size_t)BB * TT * VD];
__device__ float g_h1[BB * FD];
__device__ float g_h2[BB * FD];
__device__ float g_part[(size_t)32 * BB * FD];   // 8.39M floats: max split-K partials

// ---------------- tf32 mma helpers ----------------
__device__ __forceinline__ uint32_t f2tf(float f) {
    uint32_t u;
    asm("cvt.rna.tf32.f32 %0, %1;" : "=r"(u) : "f"(f));
    return u;
}

__device__ __forceinline__ void mma8(float* c, const uint32_t* a, uint32_t b0, uint32_t b1) {
    asm volatile(
        "mma.sync.aligned.m16n8k8.row.col.f32.tf32.tf32.f32 "
        "{%0,%1,%2,%3},{%4,%5,%6,%7},{%8,%9},{%0,%1,%2,%3};"
        : "+f"(c[0]), "+f"(c[1]), "+f"(c[2]), "+f"(c[3])
        : "r"(a[0]), "r"(a[1]), "r"(a[2]), "r"(a[3]), "r"(b0), "r"(b1));
}

// ---------------- generic tf32 GEMM ----------------
// C[M,N] (+= split partials) = A[M,K] @ B[K,N], all row-major fp32.
// grid: x = N/128 tiles, y = M/128 tiles, z = K splits (kchunk = K/splits, mult of 32).
// splits==1: fused bias (+ optional sigmoid) epilogue, write to C.
// splits>1 : raw partial accumulators written to C + z*M*N.
__global__ __launch_bounds__(256) void gemm_tf32_kernel(
    const float* __restrict__ A, const float* __restrict__ Bm,
    float* __restrict__ C, const float* __restrict__ bias,
    int M, int N, int K, int act)
{
    __shared__ float As[128][36];    // pad 36 -> conflict-free frag reads
    __shared__ float Bs[32][132];

    const int splits = gridDim.z;
    const int kchunk = K / splits;
    const int kbeg = blockIdx.z * kchunk;
    const int m0 = blockIdx.y * 128;
    const int n0 = blockIdx.x * 128;
    const int tid = threadIdx.x;
    const int warp = tid >> 5, lane = tid & 31;
    const int wm = warp & 3, wn = warp >> 2;      // 4 (M) x 2 (N) warps; warp tile 32x64
    const int gi = lane >> 2, tg = lane & 3;

    float acc[2][8][4];
#pragma unroll
    for (int i = 0; i < 2; i++)
#pragma unroll
        for (int j = 0; j < 8; j++)
#pragma unroll
            for (int x = 0; x < 4; x++) acc[i][j][x] = 0.f;

    for (int k0 = 0; k0 < kchunk; k0 += 32) {
        const int kb = kbeg + k0;
        // stage A[128][32]
#pragma unroll
        for (int it = 0; it < 4; it++) {
            int idx = tid + it * 256;
            int row = idx >> 3;
            int c4 = (idx & 7) << 2;
            float4 vA = *reinterpret_cast<const float4*>(A + (size_t)(m0 + row) * K + kb + c4);
            *reinterpret_cast<float4*>(&As[row][c4]) = vA;
        }
        // stage B[32][128]
#pragma unroll
        for (int it = 0; it < 4; it++) {
            int idx = tid + it * 256;
            int row = idx >> 5;
            int c4 = (idx & 31) << 2;
            float4 vB = *reinterpret_cast<const float4*>(Bm + (size_t)(kb + row) * N + n0 + c4);
            *reinterpret_cast<float4*>(&Bs[row][c4]) = vB;
        }
        __syncthreads();
#pragma unroll
        for (int kk = 0; kk < 32; kk += 8) {
            uint32_t a[2][4];
#pragma unroll
            for (int mi = 0; mi < 2; mi++) {
                int r0 = wm * 32 + mi * 16;
                a[mi][0] = f2tf(As[r0 + gi][kk + tg]);
                a[mi][1] = f2tf(As[r0 + gi + 8][kk + tg]);
                a[mi][2] = f2tf(As[r0 + gi][kk + tg + 4]);
                a[mi][3] = f2tf(As[r0 + gi + 8][kk + tg + 4]);
            }
#pragma unroll
            for (int ni = 0; ni < 8; ni++) {
                int c0 = wn * 64 + ni * 8;
                uint32_t b0 = f2tf(Bs[kk + tg][c0 + gi]);
                uint32_t b1 = f2tf(Bs[kk + tg + 4][c0 + gi]);
                mma8(acc[0][ni], a[0], b0, b1);
                mma8(acc[1][ni], a[1], b0, b1);
            }
        }
        __syncthreads();
    }

    const bool fused = (splits == 1);
    float* Cout = C + (size_t)blockIdx.z * (size_t)M * (size_t)N;
#pragma unroll
    for (int mi = 0; mi < 2; mi++) {
#pragma unroll
        for (int ni = 0; ni < 8; ni++) {
            int row = m0 + wm * 32 + mi * 16 + gi;
            int col = n0 + wn * 64 + ni * 8 + tg * 2;
            float c0 = acc[mi][ni][0], c1 = acc[mi][ni][1];
            float c2 = acc[mi][ni][2], c3 = acc[mi][ni][3];
            if (fused) {
                float bv0 = bias ? bias[col] : 0.f;
                float bv1 = bias ? bias[col + 1] : 0.f;
                c0 += bv0; c1 += bv1; c2 += bv0; c3 += bv1;
                if (act == 1) {
                    c0 = 1.f / (1.f + __expf(-c0));
                    c1 = 1.f / (1.f + __expf(-c1));
                    c2 = 1.f / (1.f + __expf(-c2));
                    c3 = 1.f / (1.f + __expf(-c3));
                }
            }
            Cout[(size_t)row * N + col] = c0;
            Cout[(size_t)row * N + col + 1] = c1;
            Cout[(size_t)(row + 8) * N + col] = c2;
            Cout[(size_t)(row + 8) * N + col + 1] = c3;
        }
    }
}

// ---------------- split reduce + bias + activation ----------------
__global__ __launch_bounds__(256) void reduce_kernel(
    const float* __restrict__ part, const float* __restrict__ bias,
    float* __restrict__ out, int MN, int N, int splits, int act)
{
    int i = blockIdx.x * 256 + threadIdx.x;
    if (i >= MN) return;
    float s = 0.f;
    for (int z = 0; z < splits; z++) s += part[(size_t)z * MN + i];
    s += bias[i % N];
    if (act) s = 1.f / (1.f + __expf(-s));
    out[i] = s;
}

// ---------------- attention: softmax(K Q^T) V  (no 1/sqrt(d) scale) ----------------
// grid (4, 128): 64-row t-tile per CTA, one batch per blockIdx.y. 256 threads.
#define ATTN_SMEM_BYTES ((64 * 132 + 64 * 260 + 128 * 132 + 64) * 4)

__global__ __launch_bounds__(256) void attn_kernel(
    const float* __restrict__ q, const float* __restrict__ k,
    const float* __restrict__ v, float* __restrict__ r)
{
    extern __shared__ float sm[];
    float* kt = sm;                    // [64][132]  k rows (the "query" of this softmax)
    float* S = sm + 64 * 132;          // [64][260]  scores -> exp
    float* qs = S + 64 * 260;          // [128][132] q chunk, reused for v chunk
    float* rs = qs + 128 * 132;        // [64]       1/rowsum

    const int b = blockIdx.y;
    const int t0 = blockIdx.x * 64;
    const float* kb = k + ((size_t)b * TT + t0) * KD;
    const float* qb = q + (size_t)b * TT * KD;
    const float* vb = v + (size_t)b * TT * VD;
    const int tid = threadIdx.x, warp = tid >> 5, lane = tid & 31;
    const int gi = lane >> 2, tg = lane & 3;
    const int wm = warp & 1, wn = warp >> 1;      // 2 (M) x 4 (N) warps; warp tile 32x32

    // stage k tile [64][128]
#pragma unroll
    for (int it = 0; it < 8; it++) {
        int idx = tid + it * 256;
        int row = idx >> 5;
        int c4 = (idx & 31) << 2;
        *reinterpret_cast<float4*>(&kt[row * 132 + c4]) =
            *reinterpret_cast<const float4*>(kb + (size_t)row * KD + c4);
    }

    // ---- phase 1: S[t, s] = kt[t,:] . q[s,:] ----
    for (int sc = 0; sc < 2; sc++) {
        __syncthreads();
#pragma unroll
        for (int it = 0; it < 16; it++) {
            int idx = tid + it * 256;
            int row = idx >> 5;
            int c4 = (idx & 31) << 2;
            *reinterpret_cast<float4*>(&qs[row * 132 + c4]) =
                *reinterpret_cast<const float4*>(qb + (size_t)(sc * 128 + row) * KD + c4);
        }
        __syncthreads();
        float acc[2][4][4];
#pragma unroll
        for (int i = 0; i < 2; i++)
#pragma unroll
            for (int j = 0; j < 4; j++)
#pragma unroll
                for (int x = 0; x < 4; x++) acc[i][j][x] = 0.f;
#pragma unroll
        for (int kk = 0; kk < 128; kk += 8) {
            uint32_t a[2][4];
#pragma unroll
            for (int mi = 0; mi < 2; mi++) {
                int r0 = wm * 32 + mi * 16;
                a[mi][0] = f2tf(kt[(r0 + gi) * 132 + kk + tg]);
                a[mi][1] = f2tf(kt[(r0 + gi + 8) * 132 + kk + tg]);
                a[mi][2] = f2tf(kt[(r0 + gi) * 132 + kk + tg + 4]);
                a[mi][3] = f2tf(kt[(r0 + gi + 8) * 132 + kk + tg + 4]);
            }
#pragma unroll
            for (int ni = 0; ni < 4; ni++) {
                int c0 = wn * 32 + ni * 8;
                // B[k][n] = q[s=n][k]  (transposed read)
                uint32_t b0 = f2tf(qs[(c0 + gi) * 132 + kk + tg]);
                uint32_t b1 = f2tf(qs[(c0 + gi) * 132 + kk + tg + 4]);
                mma8(acc[0][ni], a[0], b0, b1);
                mma8(acc[1][ni], a[1], b0, b1);
            }
        }
#pragma unroll
        for (int mi = 0; mi < 2; mi++)
#pragma unroll
            for (int ni = 0; ni < 4; ni++) {
                int row = wm * 32 + mi * 16 + gi;
                int col = sc * 128 + wn * 32 + ni * 8 + tg * 2;
                S[row * 260 + col] = acc[mi][ni][0];
                S[row * 260 + col + 1] = acc[mi][ni][1];
                S[(row + 8) * 260 + col] = acc[mi][ni][2];
                S[(row + 8) * 260 + col + 1] = acc[mi][ni][3];
            }
    }
    __syncthreads();

    // ---- phase 2: row softmax (store exp, keep 1/rowsum) ----
#pragma unroll
    for (int rr = 0; rr < 8; rr++) {
        int row = warp * 8 + rr;
        float m = -1e30f;
        for (int j = lane; j < 256; j += 32) m = fmaxf(m, S[row * 260 + j]);
#pragma unroll
        for (int o = 16; o; o >>= 1) m = fmaxf(m, __shfl_xor_sync(0xffffffffu, m, o));
        float sum = 0.f;
        for (int j = lane; j < 256; j += 32) {
            float e = __expf(S[row * 260 + j] - m);
            S[row * 260 + j] = e;
            sum += e;
        }
#pragma unroll
        for (int o = 16; o; o >>= 1) sum += __shfl_xor_sync(0xffffffffu, sum, o);
        if (lane == 0) rs[row] = 1.f / sum;
    }
    __syncthreads();

    // ---- phase 3: r = exp(S) @ v, scaled by 1/rowsum ----
    float acc[2][4][4];
#pragma unroll
    for (int i = 0; i < 2; i++)
#pragma unroll
        for (int j = 0; j < 4; j++)
#pragma unroll
            for (int x = 0; x < 4; x++) acc[i][j][x] = 0.f;

    for (int sc = 0; sc < 2; sc++) {
#pragma unroll
        for (int it = 0; it < 16; it++) {
            int idx = tid + it * 256;
            int row = idx >> 5;
            int c4 = (idx & 31) << 2;
            *reinterpret_cast<float4*>(&qs[row * 132 + c4]) =
                *reinterpret_cast<const float4*>(vb + (size_t)(sc * 128 + row) * VD + c4);
        }
        __syncthreads();
#pragma unroll
        for (int kk = 0; kk < 128; kk += 8) {
            uint32_t a[2][4];
#pragma unroll
            for (int mi = 0; mi < 2; mi++) {
                int r0 = wm * 32 + mi * 16;
                a[mi][0] = f2tf(S[(r0 + gi) * 260 + sc * 128 + kk + tg]);
                a[mi][1] = f2tf(S[(r0 + gi + 8) * 260 + sc * 128 + kk + tg]);
                a[mi][2] = f2tf(S[(r0 + gi) * 260 + sc * 128 + kk + tg + 4]);
                a[mi][3] = f2tf(S[(r0 + gi + 8) * 260 + sc * 128 + kk + tg + 4]);
            }
#pragma unroll
            for (int ni = 0; ni < 4; ni++) {
                int c0 = wn * 32 + ni * 8;
                uint32_t b0 = f2tf(qs[(kk + tg) * 132 + c0 + gi]);
                uint32_t b1 = f2tf(qs[(kk + tg + 4) * 132 + c0 + gi]);
                mma8(acc[0][ni], a[0], b0, b1);
                mma8(acc[1][ni], a[1], b0, b1);
            }
        }
        __syncthreads();
    }

    float* rb = r + ((size_t)b * TT + t0) * VD;
#pragma unroll
    for (int mi = 0; mi < 2; mi++)
#pragma unroll
        for (int ni = 0; ni < 4; ni++) {
            int row = wm * 32 + mi * 16 + gi;
            int col = wn * 32 + ni * 8 + tg * 2;
            float s0 = rs[row], s1 = rs[row + 8];
            rb[(size_t)row * VD + col] = acc[mi][ni][0] * s0;
            rb[(size_t)row * VD + col + 1] = acc[mi][ni][1] * s0;
            rb[(size_t)(row + 8) * VD + col] = acc[mi][ni][2] * s1;
            rb[(size_t)(row + 8) * VD + col + 1] = acc[mi][ni][3] * s1;
        }
}

// ---------------- launch ----------------
extern "C" void kernel_launch(void* const* d_in, const int* in_sizes, int n_in,
                              void* d_out, int out_size)
{
    const float* X  = (const float*)d_in[0];
    const float* Qw = (const float*)d_in[1];
    const float* Qb = (const float*)d_in[2];
    const float* Kw = (const float*)d_in[3];
    const float* Kb = (const float*)d_in[4];
    const float* Vw = (const float*)d_in[5];
    const float* Vb = (const float*)d_in[6];
    const float* W1 = (const float*)d_in[7];
    const float* b1 = (const float*)d_in[8];
    const float* W2 = (const float*)d_in[9];
    const float* b2 = (const float*)d_in[10];
    const float* W3 = (const float*)d_in[11];
    const float* b3 = (const float*)d_in[12];
    float* out = (float*)d_out;

    float *qp, *kp, *vp, *rp, *h1p, *h2p, *pp;
    cudaGetSymbolAddress((void**)&qp, g_q);
    cudaGetSymbolAddress((void**)&kp, g_k);
    cudaGetSymbolAddress((void**)&vp, g_v);
    cudaGetSymbolAddress((void**)&rp, g_r);
    cudaGetSymbolAddress((void**)&h1p, g_h1);
    cudaGetSymbolAddress((void**)&h2p, g_h2);
    cudaGetSymbolAddress((void**)&pp, g_part);

    cudaFuncSetAttribute(attn_kernel, cudaFuncAttributeMaxDynamicSharedMemorySize,
                         ATTN_SMEM_BYTES);

    dim3 thr(256);

    // QKV projections: [32768,128] @ [128,128] + bias (fused)
    gemm_tf32_kernel<<<dim3(1, 256, 1), thr>>>(X, Qw, qp, Qb, BB * TT, KD, ND, 0);
    gemm_tf32_kernel<<<dim3(1, 256, 1), thr>>>(X, Kw, kp, Kb, BB * TT, KD, ND, 0);
    gemm_tf32_kernel<<<dim3(1, 256, 1), thr>>>(X, Vw, vp, Vb, BB * TT, VD, ND, 0);

    // attention
    attn_kernel<<<dim3(4, 128), thr, ATTN_SMEM_BYTES>>>(qp, kp, vp, rp);

    // MLP layer 1: [128, 32768] @ [32768, 2048], split-K 32 + sigmoid reduce
    gemm_tf32_kernel<<<dim3(FD / 128, 1, 32), thr>>>(rp, W1, pp, nullptr, BB, FD, TT * VD, 0);
    reduce_kernel<<<(BB * FD + 255) / 256, 256>>>(pp, b1, h1p, BB * FD, FD, 32, 1);

    // MLP layer 2: [128, 2048] @ [2048, 2048], split-K 8 + sigmoid reduce
    gemm_tf32_kernel<<<dim3(FD / 128, 1, 8), thr>>>(h1p, W2, pp, nullptr, BB, FD, FD, 0);
    reduce_kernel<<<(BB * FD + 255) / 256, 256>>>(pp, b2, h2p, BB * FD, FD, 8, 1);

    // MLP layer 3: [128, 2048] @ [2048, 4096], split-K 8 + bias (no act) -> out
    gemm_tf32_kernel<<<dim3(OD / 128, 1, 8), thr>>>(h2p, W3, pp, nullptr, BB, OD, FD, 0);
    reduce_kernel<<<(BB * OD + 255) / 256, 256>>>(pp, b3, out, BB * OD, OD, 8, 0);
}

// round 2
// speedup vs baseline: 1.0873x; 1.0873x over previous
#include <cuda_runtime.h>
#include <cstdint>

// ---------------- problem dims ----------------
#define BB 128
#define TT 256
#define ND 128
#define KD 128
#define VD 128
#define FD 2048
#define OD 4096   // ODIM*NDIM
#define SQ 384    // fused qkv row stride

// ---------------- device scratch (no allocations allowed) ----------------
__device__ float g_qkv[(size_t)BB * TT * SQ];    // fused q|k|v, stride 384
__device__ float g_wqkv[ND * SQ];                // packed [128][384] weight
__device__ float g_bqkv[SQ];
__device__ float g_r[(size_t)BB * TT * VD];
__device__ float g_h1[BB * FD];
__device__ float g_h2[BB * FD];
__device__ float g_part[(size_t)32 * BB * FD];   // split-K partials (max 8.39M floats)

// ---------------- tf32 mma helpers ----------------
__device__ __forceinline__ uint32_t f2tf(float f) {
    uint32_t u;
    asm("cvt.rna.tf32.f32 %0, %1;" : "=r"(u) : "f"(f));
    return u;
}
__device__ __forceinline__ float f2tff(float f) { return __uint_as_float(f2tf(f)); }

__device__ __forceinline__ void mma8(float* c, const uint32_t* a, uint32_t b0, uint32_t b1) {
    asm volatile(
        "mma.sync.aligned.m16n8k8.row.col.f32.tf32.tf32.f32 "
        "{%0,%1,%2,%3},{%4,%5,%6,%7},{%8,%9},{%0,%1,%2,%3};"
        : "+f"(c[0]), "+f"(c[1]), "+f"(c[2]), "+f"(c[3])
        : "r"(a[0]), "r"(a[1]), "r"(a[2]), "r"(a[3]), "r"(b0), "r"(b1));
}

__device__ __forceinline__ void cp16(void* dst, const void* src) {
    uint32_t d = (uint32_t)__cvta_generic_to_shared(dst);
    asm volatile("cp.async.cg.shared.global [%0], [%1], 16;" :: "r"(d), "l"(src));
}
__device__ __forceinline__ void cp_commit() { asm volatile("cp.async.commit_group;"); }
template <int N> __device__ __forceinline__ void cp_wait() {
    asm volatile("cp.async.wait_group %0;" :: "n"(N));
}

// ---------------- pack QKV weights ----------------
__global__ void pack_qkv_kernel(
    const float* __restrict__ Qw, const float* __restrict__ Kw, const float* __restrict__ Vw,
    const float* __restrict__ Qb, const float* __restrict__ Kb, const float* __restrict__ Vb,
    float* __restrict__ w, float* __restrict__ bia)
{
    int idx = blockIdx.x * 256 + threadIdx.x;
    if (idx < ND * SQ) {
        int k = idx / SQ, c = idx % SQ;
        float v;
        if (c < 128)       v = Qw[k * 128 + c];
        else if (c < 256)  v = Kw[k * 128 + c - 128];
        else               v = Vw[k * 128 + c - 256];
        w[idx] = v;
    }
    if (idx < SQ) {
        float v;
        if (idx < 128)      v = Qb[idx];
        else if (idx < 256) v = Kb[idx - 128];
        else                v = Vb[idx - 256];
        bia[idx] = v;
    }
}

// ---------------- pipelined tf32 GEMM ----------------
// C[M,N] = A[M,K] @ B[K,N] row-major fp32. CTA tile 128x128, kstep 32, 2-stage cp.async.
// grid: x = N/128, y = M/128, z = splits (kchunk = K/splits, multiple of 32).
// splits==1: fused bias (+sigmoid if act) into C. splits>1: raw partials at C + z*M*N.
#define GEMM_SMEM ((2 * 128 * 36 + 2 * 32 * 132) * 4)

__global__ __launch_bounds__(256, 2) void gemm_tf32_pipe(
    const float* __restrict__ A, const float* __restrict__ Bm,
    float* __restrict__ C, const float* __restrict__ bias,
    int M, int N, int K, int act)
{
    extern __shared__ float smp[];
    float* As = smp;                    // [2][128][36]
    float* Bs = smp + 2 * 128 * 36;     // [2][32][132]

    const int splits = gridDim.z;
    const int kchunk = K / splits;
    const int kbeg = blockIdx.z * kchunk;
    const int m0 = blockIdx.y * 128;
    const int n0 = blockIdx.x * 128;
    const int tid = threadIdx.x;
    const int warp = tid >> 5, lane = tid & 31;
    const int wm = warp & 3, wn = warp >> 2;      // 4(M) x 2(N); warp tile 32x64
    const int gi = lane >> 2, tg = lane & 3;

    float acc[2][8][4];
#pragma unroll
    for (int i = 0; i < 2; i++)
#pragma unroll
        for (int j = 0; j < 8; j++)
#pragma unroll
            for (int x = 0; x < 4; x++) acc[i][j][x] = 0.f;

    // stage addresses (constant per thread)
    const int ar = tid >> 3, ac = (tid & 7) << 2;    // A: 32 rows per it-pass? no: 256 thr cover 128x32/4 per pass
    const int br = tid >> 5, bc = (tid & 31) << 2;

    auto stage = [&](int s, int kb) {
        float* as = As + s * (128 * 36);
        float* bs = Bs + s * (32 * 132);
#pragma unroll
        for (int it = 0; it < 4; it++) {
            int row = ar + it * 32;                 // tid>>3 in [0,32) ; 4 passes -> 128 rows
            cp16(&as[row * 36 + ac], A + (size_t)(m0 + row) * K + kb + ac);
        }
#pragma unroll
        for (int it = 0; it < 4; it++) {
            int row = br + it * 8;                  // tid>>5 in [0,8) ; 4 passes -> 32 rows
            cp16(&bs[row * 132 + bc], Bm + (size_t)(kb + row) * N + n0 + bc);
        }
        cp_commit();
    };

    const int nsteps = kchunk / 32;
    stage(0, kbeg);

    for (int s = 0; s < nsteps; s++) {
        if (s + 1 < nsteps) { stage((s + 1) & 1, kbeg + (s + 1) * 32); cp_wait<1>(); }
        else cp_wait<0>();
        __syncthreads();
        float* as = As + (s & 1) * (128 * 36);
        float* bs = Bs + (s & 1) * (32 * 132);
#pragma unroll
        for (int kk = 0; kk < 32; kk += 8) {
            uint32_t a[2][4];
#pragma unroll
            for (int mi = 0; mi < 2; mi++) {
                int r0 = wm * 32 + mi * 16;
                a[mi][0] = f2tf(as[(r0 + gi) * 36 + kk + tg]);
                a[mi][1] = f2tf(as[(r0 + gi + 8) * 36 + kk + tg]);
                a[mi][2] = f2tf(as[(r0 + gi) * 36 + kk + tg + 4]);
                a[mi][3] = f2tf(as[(r0 + gi + 8) * 36 + kk + tg + 4]);
            }
#pragma unroll
            for (int ni = 0; ni < 8; ni++) {
                int c0 = wn * 64 + ni * 8;
                uint32_t b0 = f2tf(bs[(kk + tg) * 132 + c0 + gi]);
                uint32_t b1 = f2tf(bs[(kk + tg + 4) * 132 + c0 + gi]);
                mma8(acc[0][ni], a[0], b0, b1);
                mma8(acc[1][ni], a[1], b0, b1);
            }
        }
        __syncthreads();
    }

    const bool fused = (splits == 1);
    float* Cout = C + (size_t)blockIdx.z * (size_t)M * (size_t)N;
#pragma unroll
    for (int mi = 0; mi < 2; mi++) {
#pragma unroll
        for (int ni = 0; ni < 8; ni++) {
            int row = m0 + wm * 32 + mi * 16 + gi;
            int col = n0 + wn * 64 + ni * 8 + tg * 2;
            float c0 = acc[mi][ni][0], c1 = acc[mi][ni][1];
            float c2 = acc[mi][ni][2], c3 = acc[mi][ni][3];
            if (fused) {
                float bv0 = bias ? bias[col] : 0.f;
                float bv1 = bias ? bias[col + 1] : 0.f;
                c0 += bv0; c1 += bv1; c2 += bv0; c3 += bv1;
                if (act == 1) {
                    c0 = 1.f / (1.f + __expf(-c0));
                    c1 = 1.f / (1.f + __expf(-c1));
                    c2 = 1.f / (1.f + __expf(-c2));
                    c3 = 1.f / (1.f + __expf(-c3));
                }
            }
            Cout[(size_t)row * N + col] = c0;
            Cout[(size_t)row * N + col + 1] = c1;
            Cout[(size_t)(row + 8) * N + col] = c2;
            Cout[(size_t)(row + 8) * N + col + 1] = c3;
        }
    }
}

// ---------------- split reduce + bias + activation ----------------
__global__ __launch_bounds__(256) void reduce_kernel(
    const float* __restrict__ part, const float* __restrict__ bias,
    float* __restrict__ out, int MN, int N, int splits, int act)
{
    int i = blockIdx.x * 256 + threadIdx.x;
    if (i >= MN) return;
    float s = 0.f;
    for (int z = 0; z < splits; z++) s += part[(size_t)z * MN + i];
    s += bias[i % N];
    if (act) s = 1.f / (1.f + __expf(-s));
    out[i] = s;
}

// ---------------- attention: softmax(K Q^T) V ----------------
// grid (4, 128): 64-row t-tile, one batch per blockIdx.y. 256 threads.
// All smem operands are pre-rounded to tf32 at staging time -> inner loop is LDS+MMA only.
#define ATTN_SMEM_BYTES ((64 * 132 + 64 * 260 + 128 * 132 + 64) * 4)

__global__ __launch_bounds__(256) void attn_kernel(
    const float* __restrict__ qkv, float* __restrict__ r)
{
    extern __shared__ float sm[];
    float* kt = sm;                    // [64][132]  tf32-rounded k rows
    float* S = sm + 64 * 132;          // [64][260]  scores -> rounded exp
    float* qs = S + 64 * 260;          // [128][132] q chunk (rounded), reused for v
    float* rs = qs + 128 * 132;        // [64]       1/rowsum

    const int b = blockIdx.y;
    const int t0 = blockIdx.x * 64;
    const float* qb = qkv + (size_t)b * TT * SQ;                 // stride SQ
    const float* kb = qkv + ((size_t)b * TT + t0) * SQ + 128;
    const float* vb = qkv + (size_t)b * TT * SQ + 256;
    const int tid = threadIdx.x, warp = tid >> 5, lane = tid & 31;
    const int gi = lane >> 2, tg = lane & 3;
    const int wm = warp & 1, wn = warp >> 1;      // 2(M) x 4(N); warp tile 32x32

    // stage k tile [64][128], rounded
#pragma unroll
    for (int it = 0; it < 8; it++) {
        int idx = tid + it * 256;
        int row = idx >> 5;
        int c4 = (idx & 31) << 2;
        float4 v4 = *reinterpret_cast<const float4*>(kb + (size_t)row * SQ + c4);
        v4.x = f2tff(v4.x); v4.y = f2tff(v4.y); v4.z = f2tff(v4.z); v4.w = f2tff(v4.w);
        *reinterpret_cast<float4*>(&kt[row * 132 + c4]) = v4;
    }

    // ---- phase 1: S[t, s] = kt[t,:] . q[s,:] ----
    for (int sc = 0; sc < 2; sc++) {
        __syncthreads();
#pragma unroll
        for (int it = 0; it < 16; it++) {
            int idx = tid + it * 256;
            int row = idx >> 5;
            int c4 = (idx & 31) << 2;
            float4 v4 = *reinterpret_cast<const float4*>(qb + (size_t)(sc * 128 + row) * SQ + c4);
            v4.x = f2tff(v4.x); v4.y = f2tff(v4.y); v4.z = f2tff(v4.z); v4.w = f2tff(v4.w);
            *reinterpret_cast<float4*>(&qs[row * 132 + c4]) = v4;
        }
        __syncthreads();
        float acc[2][4][4];
#pragma unroll
        for (int i = 0; i < 2; i++)
#pragma unroll
            for (int j = 0; j < 4; j++)
#pragma unroll
                for (int x = 0; x < 4; x++) acc[i][j][x] = 0.f;
#pragma unroll
        for (int kk = 0; kk < 128; kk += 8) {
            uint32_t a[2][4];
#pragma unroll
            for (int mi = 0; mi < 2; mi++) {
                int r0 = wm * 32 + mi * 16;
                a[mi][0] = __float_as_uint(kt[(r0 + gi) * 132 + kk + tg]);
                a[mi][1] = __float_as_uint(kt[(r0 + gi + 8) * 132 + kk + tg]);
                a[mi][2] = __float_as_uint(kt[(r0 + gi) * 132 + kk + tg + 4]);
                a[mi][3] = __float_as_uint(kt[(r0 + gi + 8) * 132 + kk + tg + 4]);
            }
#pragma unroll
            for (int ni = 0; ni < 4; ni++) {
                int c0 = wn * 32 + ni * 8;
                uint32_t b0 = __float_as_uint(qs[(c0 + gi) * 132 + kk + tg]);
                uint32_t b1 = __float_as_uint(qs[(c0 + gi) * 132 + kk + tg + 4]);
                mma8(acc[0][ni], a[0], b0, b1);
                mma8(acc[1][ni], a[1], b0, b1);
            }
        }
#pragma unroll
        for (int mi = 0; mi < 2; mi++)
#pragma unroll
            for (int ni = 0; ni < 4; ni++) {
                int row = wm * 32 + mi * 16 + gi;
                int col = sc * 128 + wn * 32 + ni * 8 + tg * 2;
                S[row * 260 + col] = acc[mi][ni][0];
                S[row * 260 + col + 1] = acc[mi][ni][1];
                S[(row + 8) * 260 + col] = acc[mi][ni][2];
                S[(row + 8) * 260 + col + 1] = acc[mi][ni][3];
            }
    }
    __syncthreads();

    // ---- phase 2: row softmax; store tf32-rounded exp, keep 1/rowsum ----
#pragma unroll
    for (int rr = 0; rr < 8; rr++) {
        int row = warp * 8 + rr;
        float m = -1e30f;
        for (int j = lane; j < 256; j += 32) m = fmaxf(m, S[row * 260 + j]);
#pragma unroll
        for (int o = 16; o; o >>= 1) m = fmaxf(m, __shfl_xor_sync(0xffffffffu, m, o));
        float sum = 0.f;
        for (int j = lane; j < 256; j += 32) {
            float e = f2tff(__expf(S[row * 260 + j] - m));
            S[row * 260 + j] = e;
            sum += e;
        }
#pragma unroll
        for (int o = 16; o; o >>= 1) sum += __shfl_xor_sync(0xffffffffu, sum, o);
        if (lane == 0) rs[row] = 1.f / sum;
    }
    __syncthreads();

    // ---- phase 3: r = exp(S) @ v, scaled by 1/rowsum ----
    float acc[2][4][4];
#pragma unroll
    for (int i = 0; i < 2; i++)
#pragma unroll
        for (int j = 0; j < 4; j++)
#pragma unroll
            for (int x = 0; x < 4; x++) acc[i][j][x] = 0.f;

    for (int sc = 0; sc < 2; sc++) {
#pragma unroll
        for (int it = 0; it < 16; it++) {
            int idx = tid + it * 256;
            int row = idx >> 5;
            int c4 = (idx & 31) << 2;
            float4 v4 = *reinterpret_cast<const float4*>(vb + (size_t)(sc * 128 + row) * SQ + c4);
            v4.x = f2tff(v4.x); v4.y = f2tff(v4.y); v4.z = f2tff(v4.z); v4.w = f2tff(v4.w);
            *reinterpret_cast<float4*>(&qs[row * 132 + c4]) = v4;
        }
        __syncthreads();
#pragma unroll
        for (int kk = 0; kk < 128; kk += 8) {
            uint32_t a[2][4];
#pragma unroll
            for (int mi = 0; mi < 2; mi++) {
                int r0 = wm * 32 + mi * 16;
                a[mi][0] = __float_as_uint(S[(r0 + gi) * 260 + sc * 128 + kk + tg]);
                a[mi][1] = __float_as_uint(S[(r0 + gi + 8) * 260 + sc * 128 + kk + tg]);
                a[mi][2] = __float_as_uint(S[(r0 + gi) * 260 + sc * 128 + kk + tg + 4]);
                a[mi][3] = __float_as_uint(S[(r0 + gi + 8) * 260 + sc * 128 + kk + tg + 4]);
            }
#pragma unroll
            for (int ni = 0; ni < 4; ni++) {
                int c0 = wn * 32 + ni * 8;
                uint32_t b0 = __float_as_uint(qs[(kk + tg) * 132 + c0 + gi]);
                uint32_t b1 = __float_as_uint(qs[(kk + tg + 4) * 132 + c0 + gi]);
                mma8(acc[0][ni], a[0], b0, b1);
                mma8(acc[1][ni], a[1], b0, b1);
            }
        }
        __syncthreads();
    }

    float* rb = r + ((size_t)b * TT + t0) * VD;
#pragma unroll
    for (int mi = 0; mi < 2; mi++)
#pragma unroll
        for (int ni = 0; ni < 4; ni++) {
            int row = wm * 32 + mi * 16 + gi;
            int col = wn * 32 + ni * 8 + tg * 2;
            float s0 = rs[row], s1 = rs[row + 8];
            rb[(size_t)row * VD + col] = acc[mi][ni][0] * s0;
            rb[(size_t)row * VD + col + 1] = acc[mi][ni][1] * s0;
            rb[(size_t)(row + 8) * VD + col] = acc[mi][ni][2] * s1;
            rb[(size_t)(row + 8) * VD + col + 1] = acc[mi][ni][3] * s1;
        }
}

// ---------------- launch ----------------
extern "C" void kernel_launch(void* const* d_in, const int* in_sizes, int n_in,
                              void* d_out, int out_size)
{
    const float* X  = (const float*)d_in[0];
    const float* Qw = (const float*)d_in[1];
    const float* Qb = (const float*)d_in[2];
    const float* Kw = (const float*)d_in[3];
    const float* Kb = (const float*)d_in[4];
    const float* Vw = (const float*)d_in[5];
    const float* Vb = (const float*)d_in[6];
    const float* W1 = (const float*)d_in[7];
    const float* b1 = (const float*)d_in[8];
    const float* W2 = (const float*)d_in[9];
    const float* b2 = (const float*)d_in[10];
    const float* W3 = (const float*)d_in[11];
    const float* b3 = (const float*)d_in[12];
    float* out = (float*)d_out;

    float *qkvp, *wp, *bp, *rp, *h1p, *h2p, *pp;
    cudaGetSymbolAddress((void**)&qkvp, g_qkv);
    cudaGetSymbolAddress((void**)&wp, g_wqkv);
    cudaGetSymbolAddress((void**)&bp, g_bqkv);
    cudaGetSymbolAddress((void**)&rp, g_r);
    cudaGetSymbolAddress((void**)&h1p, g_h1);
    cudaGetSymbolAddress((void**)&h2p, g_h2);
    cudaGetSymbolAddress((void**)&pp, g_part);

    cudaFuncSetAttribute(attn_kernel, cudaFuncAttributeMaxDynamicSharedMemorySize,
                         ATTN_SMEM_BYTES);
    cudaFuncSetAttribute(gemm_tf32_pipe, cudaFuncAttributeMaxDynamicSharedMemorySize,
                         GEMM_SMEM);

    dim3 thr(256);

    // pack fused QKV weight + bias
    pack_qkv_kernel<<<(ND * SQ + 255) / 256, thr>>>(Qw, Kw, Vw, Qb, Kb, Vb, wp, bp);

    // fused QKV projection: [32768,128] @ [128,384] + bias, output stride 384
    gemm_tf32_pipe<<<dim3(3, 256, 1), thr, GEMM_SMEM>>>(X, wp, qkvp, bp, BB * TT, SQ, ND, 0);

    // attention
    attn_kernel<<<dim3(4, 128), thr, ATTN_SMEM_BYTES>>>(qkvp, rp);

    // MLP layer 1: [128, 32768] @ [32768, 2048], split-K 32 + sigmoid reduce
    gemm_tf32_pipe<<<dim3(FD / 128, 1, 32), thr, GEMM_SMEM>>>(rp, W1, pp, nullptr, BB, FD, TT * VD, 0);
    reduce_kernel<<<(BB * FD + 255) / 256, 256>>>(pp, b1, h1p, BB * FD, FD, 32, 1);

    // MLP layer 2: [128, 2048] @ [2048, 2048], split-K 16 + sigmoid reduce
    gemm_tf32_pipe<<<dim3(FD / 128, 1, 16), thr, GEMM_SMEM>>>(h1p, W2, pp, nullptr, BB, FD, FD, 0);
    reduce_kernel<<<(BB * FD + 255) / 256, 256>>>(pp, b2, h2p, BB * FD, FD, 16, 1);

    // MLP layer 3: [128, 2048] @ [2048, 4096], split-K 8 + bias (no act) -> out
    gemm_tf32_pipe<<<dim3(OD / 128, 1, 8), thr, GEMM_SMEM>>>(h2p, W3, pp, nullptr, BB, OD, FD, 0);
    reduce_kernel<<<(BB * OD + 255) / 256, 256>>>(pp, b3, out, BB * OD, OD, 8, 0);
}

// round 4
// speedup vs baseline: 1.1654x; 1.0718x over previous
#include <cuda_runtime.h>
#include <cstdint>

// ---------------- problem dims ----------------
#define BB 128
#define TT 256
#define ND 128
#define KD 128
#define VD 128
#define FD 2048
#define OD 4096   // ODIM*NDIM
#define SQ 384    // fused qkv row stride

// ---------------- device scratch (no allocations allowed) ----------------
__device__ float g_qkv[(size_t)BB * TT * SQ];    // fused q|k|v, stride 384
__device__ float g_wqkv[ND * SQ];                // packed [128][384] weight
__device__ float g_bqkv[SQ];
__device__ float g_r[(size_t)BB * TT * VD];
__device__ float g_h1[BB * FD];
__device__ float g_h2[BB * FD];
__device__ float g_part[(size_t)32 * BB * FD];   // split-K partials (max 8.39M floats)

// ---------------- tf32 mma helpers ----------------
__device__ __forceinline__ uint32_t f2tf(float f) {
    uint32_t u;
    asm("cvt.rna.tf32.f32 %0, %1;" : "=r"(u) : "f"(f));
    return u;
}
__device__ __forceinline__ float f2tff(float f) { return __uint_as_float(f2tf(f)); }

__device__ __forceinline__ void mma8(float* c, const uint32_t* a, uint32_t b0, uint32_t b1) {
    asm volatile(
        "mma.sync.aligned.m16n8k8.row.col.f32.tf32.tf32.f32 "
        "{%0,%1,%2,%3},{%4,%5,%6,%7},{%8,%9},{%0,%1,%2,%3};"
        : "+f"(c[0]), "+f"(c[1]), "+f"(c[2]), "+f"(c[3])
        : "r"(a[0]), "r"(a[1]), "r"(a[2]), "r"(a[3]), "r"(b0), "r"(b1));
}

__device__ __forceinline__ void cp16(void* dst, const void* src) {
    uint32_t d = (uint32_t)__cvta_generic_to_shared(dst);
    asm volatile("cp.async.cg.shared.global [%0], [%1], 16;" :: "r"(d), "l"(src));
}
__device__ __forceinline__ void cp_commit() { asm volatile("cp.async.commit_group;"); }
template <int N> __device__ __forceinline__ void cp_wait() {
    asm volatile("cp.async.wait_group %0;" :: "n"(N));
}

// ---------------- pack QKV weights ----------------
__global__ void pack_qkv_kernel(
    const float* __restrict__ Qw, const float* __restrict__ Kw, const float* __restrict__ Vw,
    const float* __restrict__ Qb, const float* __restrict__ Kb, const float* __restrict__ Vb,
    float* __restrict__ w, float* __restrict__ bia)
{
    int idx = blockIdx.x * 256 + threadIdx.x;
    if (idx < ND * SQ) {
        int k = idx / SQ, c = idx % SQ;
        float v;
        if (c < 128)       v = Qw[k * 128 + c];
        else if (c < 256)  v = Kw[k * 128 + c - 128];
        else               v = Vw[k * 128 + c - 256];
        w[idx] = v;
    }
    if (idx < SQ) {
        float v;
        if (idx < 128)      v = Qb[idx];
        else if (idx < 256) v = Kb[idx - 128];
        else                v = Vb[idx - 256];
        bia[idx] = v;
    }
}

// ---------------- pipelined tf32 GEMM, 64x64 warp tiles ----------------
// C[M,N] = A[M,K] @ B[K,N] row-major fp32. CTA 128x128, 128 threads (4 warps 2x2),
// kstep 32, 2-stage cp.async. grid: x=N/128, y=M/128, z=splits.
// splits==1: fused bias (+sigmoid if act). splits>1: partials at C + z*M*N.
#define ASTRIDE 36
#define BSTRIDE 136
#define GEMM_SMEM ((2 * 128 * ASTRIDE + 2 * 32 * BSTRIDE) * 4)

__global__ __launch_bounds__(128, 2) void gemm_tf32_pipe(
    const float* __restrict__ A, const float* __restrict__ Bm,
    float* __restrict__ C, const float* __restrict__ bias,
    int M, int N, int K, int act)
{
    extern __shared__ float smp[];
    float* As = smp;                          // [2][128][ASTRIDE]
    float* Bs = smp + 2 * 128 * ASTRIDE;      // [2][32][BSTRIDE]

    const int splits = gridDim.z;
    const int kchunk = K / splits;
    const int kbeg = blockIdx.z * kchunk;
    const int m0 = blockIdx.y * 128;
    const int n0 = blockIdx.x * 128;
    const int tid = threadIdx.x;
    const int warp = tid >> 5, lane = tid & 31;
    const int wm = warp & 1, wn = warp >> 1;      // 2(M) x 2(N); warp tile 64x64
    const int gi = lane >> 2, tg = lane & 3;

    float acc[4][8][4];
#pragma unroll
    for (int i = 0; i < 4; i++)
#pragma unroll
        for (int j = 0; j < 8; j++)
#pragma unroll
            for (int x = 0; x < 4; x++) acc[i][j][x] = 0.f;

    auto stage = [&](int s, int kb) {
        float* as = As + s * (128 * ASTRIDE);
        float* bs = Bs + s * (32 * BSTRIDE);
#pragma unroll
        for (int it = 0; it < 8; it++) {           // A: 128x32 floats = 1024 float4
            int flat = it * 128 + tid;
            int row = flat >> 3, c4 = (flat & 7) << 2;
            cp16(&as[row * ASTRIDE + c4], A + (size_t)(m0 + row) * K + kb + c4);
        }
#pragma unroll
        for (int it = 0; it < 8; it++) {           // B: 32x128 floats = 1024 float4
            int flat = it * 128 + tid;
            int row = flat >> 5, c4 = (flat & 31) << 2;
            cp16(&bs[row * BSTRIDE + c4], Bm + (size_t)(kb + row) * N + n0 + c4);
        }
        cp_commit();
    };

    const int nsteps = kchunk / 32;
    stage(0, kbeg);

    for (int s = 0; s < nsteps; s++) {
        if (s + 1 < nsteps) { stage((s + 1) & 1, kbeg + (s + 1) * 32); cp_wait<1>(); }
        else cp_wait<0>();
        __syncthreads();
        float* as = As + (s & 1) * (128 * ASTRIDE);
        float* bs = Bs + (s & 1) * (32 * BSTRIDE);
#pragma unroll
        for (int kk = 0; kk < 32; kk += 8) {
            uint32_t a[4][4];
#pragma unroll
            for (int mi = 0; mi < 4; mi++) {
                int r0 = wm * 64 + mi * 16;
                a[mi][0] = f2tf(as[(r0 + gi) * ASTRIDE + kk + tg]);
                a[mi][1] = f2tf(as[(r0 + gi + 8) * ASTRIDE + kk + tg]);
                a[mi][2] = f2tf(as[(r0 + gi) * ASTRIDE + kk + tg + 4]);
                a[mi][3] = f2tf(as[(r0 + gi + 8) * ASTRIDE + kk + tg + 4]);
            }
            uint32_t b[8][2];
#pragma unroll
            for (int ni = 0; ni < 8; ni++) {
                int c0 = wn * 64 + ni * 8;
                b[ni][0] = f2tf(bs[(kk + tg) * BSTRIDE + c0 + gi]);
                b[ni][1] = f2tf(bs[(kk + tg + 4) * BSTRIDE + c0 + gi]);
            }
#pragma unroll
            for (int mi = 0; mi < 4; mi++)
#pragma unroll
                for (int ni = 0; ni < 8; ni++)
                    mma8(acc[mi][ni], a[mi], b[ni][0], b[ni][1]);
        }
        __syncthreads();
    }

    const bool fused = (splits == 1);
    float* Cout = C + (size_t)blockIdx.z * (size_t)M * (size_t)N;
#pragma unroll
    for (int mi = 0; mi < 4; mi++) {
#pragma unroll
        for (int ni = 0; ni < 8; ni++) {
            int row = m0 + wm * 64 + mi * 16 + gi;
            int col = n0 + wn * 64 + ni * 8 + tg * 2;
            float c0 = acc[mi][ni][0], c1 = acc[mi][ni][1];
            float c2 = acc[mi][ni][2], c3 = acc[mi][ni][3];
            if (fused) {
                float bv0 = bias ? bias[col] : 0.f;
                float bv1 = bias ? bias[col + 1] : 0.f;
                c0 += bv0; c1 += bv1; c2 += bv0; c3 += bv1;
                if (act == 1) {
                    c0 = 1.f / (1.f + __expf(-c0));
                    c1 = 1.f / (1.f + __expf(-c1));
                    c2 = 1.f / (1.f + __expf(-c2));
                    c3 = 1.f / (1.f + __expf(-c3));
                }
            }
            Cout[(size_t)row * N + col] = c0;
            Cout[(size_t)row * N + col + 1] = c1;
            Cout[(size_t)(row + 8) * N + col] = c2;
            Cout[(size_t)(row + 8) * N + col + 1] = c3;
        }
    }
}

// ---------------- split reduce + bias + activation ----------------
__global__ __launch_bounds__(256) void reduce_kernel(
    const float* __restrict__ part, const float* __restrict__ bias,
    float* __restrict__ out, int MN, int N, int splits, int act)
{
    int i = blockIdx.x * 256 + threadIdx.x;
    if (i >= MN) return;
    float s = 0.f;
    for (int z = 0; z < splits; z++) s += part[(size_t)z * MN + i];
    s += bias[i % N];
    if (act) s = 1.f / (1.f + __expf(-s));
    out[i] = s;
}

// ---------------- attention: softmax(K Q^T) V ----------------
// grid (4, 128): 64-row t-tile, one batch per blockIdx.y. 256 threads.
// All smem operands are pre-rounded to tf32 at staging time -> inner loop is LDS+MMA only.
#define ATTN_SMEM_BYTES ((64 * 132 + 64 * 260 + 128 * 132 + 64) * 4)

__global__ __launch_bounds__(256) void attn_kernel(
    const float* __restrict__ qkv, float* __restrict__ r)
{
    extern __shared__ float sm[];
    float* kt = sm;                    // [64][132]  tf32-rounded k rows
    float* S = sm + 64 * 132;          // [64][260]  scores -> rounded exp
    float* qs = S + 64 * 260;          // [128][132] q chunk (rounded), reused for v
    float* rs = qs + 128 * 132;        // [64]       1/rowsum

    const int b = blockIdx.y;
    const int t0 = blockIdx.x * 64;
    const float* qb = qkv + (size_t)b * TT * SQ;                 // stride SQ
    const float* kb = qkv + ((size_t)b * TT + t0) * SQ + 128;
    const float* vb = qkv + (size_t)b * TT * SQ + 256;
    const int tid = threadIdx.x, warp = tid >> 5, lane = tid & 31;
    const int gi = lane >> 2, tg = lane & 3;
    const int wm = warp & 1, wn = warp >> 1;      // 2(M) x 4(N); warp tile 32x32

    // stage k tile [64][128], rounded
#pragma unroll
    for (int it = 0; it < 8; it++) {
        int idx = tid + it * 256;
        int row = idx >> 5;
        int c4 = (idx & 31) << 2;
        float4 v4 = *reinterpret_cast<const float4*>(kb + (size_t)row * SQ + c4);
        v4.x = f2tff(v4.x); v4.y = f2tff(v4.y); v4.z = f2tff(v4.z); v4.w = f2tff(v4.w);
        *reinterpret_cast<float4*>(&kt[row * 132 + c4]) = v4;
    }

    // ---- phase 1: S[t, s] = kt[t,:] . q[s,:] ----
    for (int sc = 0; sc < 2; sc++) {
        __syncthreads();
#pragma unroll
        for (int it = 0; it < 16; it++) {
            int idx = tid + it * 256;
            int row = idx >> 5;
            int c4 = (idx & 31) << 2;
            float4 v4 = *reinterpret_cast<const float4*>(qb + (size_t)(sc * 128 + row) * SQ + c4);
            v4.x = f2tff(v4.x); v4.y = f2tff(v4.y); v4.z = f2tff(v4.z); v4.w = f2tff(v4.w);
            *reinterpret_cast<float4*>(&qs[row * 132 + c4]) = v4;
        }
        __syncthreads();
        float acc[2][4][4];
#pragma unroll
        for (int i = 0; i < 2; i++)
#pragma unroll
            for (int j = 0; j < 4; j++)
#pragma unroll
                for (int x = 0; x < 4; x++) acc[i][j][x] = 0.f;
#pragma unroll
        for (int kk = 0; kk < 128; kk += 8) {
            uint32_t a[2][4];
#pragma unroll
            for (int mi = 0; mi < 2; mi++) {
                int r0 = wm * 32 + mi * 16;
                a[mi][0] = __float_as_uint(kt[(r0 + gi) * 132 + kk + tg]);
                a[mi][1] = __float_as_uint(kt[(r0 + gi + 8) * 132 + kk + tg]);
                a[mi][2] = __float_as_uint(kt[(r0 + gi) * 132 + kk + tg + 4]);
                a[mi][3] = __float_as_uint(kt[(r0 + gi + 8) * 132 + kk + tg + 4]);
            }
#pragma unroll
            for (int ni = 0; ni < 4; ni++) {
                int c0 = wn * 32 + ni * 8;
                uint32_t b0 = __float_as_uint(qs[(c0 + gi) * 132 + kk + tg]);
                uint32_t b1 = __float_as_uint(qs[(c0 + gi) * 132 + kk + tg + 4]);
                mma8(acc[0][ni], a[0], b0, b1);
                mma8(acc[1][ni], a[1], b0, b1);
            }
        }
#pragma unroll
        for (int mi = 0; mi < 2; mi++)
#pragma unroll
            for (int ni = 0; ni < 4; ni++) {
                int row = wm * 32 + mi * 16 + gi;
                int col = sc * 128 + wn * 32 + ni * 8 + tg * 2;
                S[row * 260 + col] = acc[mi][ni][0];
                S[row * 260 + col + 1] = acc[mi][ni][1];
                S[(row + 8) * 260 + col] = acc[mi][ni][2];
                S[(row + 8) * 260 + col + 1] = acc[mi][ni][3];
            }
    }
    __syncthreads();

    // ---- phase 2: row softmax; store tf32-rounded exp, keep 1/rowsum ----
#pragma unroll
    for (int rr = 0; rr < 8; rr++) {
        int row = warp * 8 + rr;
        float m = -1e30f;
        for (int j = lane; j < 256; j += 32) m = fmaxf(m, S[row * 260 + j]);
#pragma unroll
        for (int o = 16; o; o >>= 1) m = fmaxf(m, __shfl_xor_sync(0xffffffffu, m, o));
        float sum = 0.f;
        for (int j = lane; j < 256; j += 32) {
            float e = f2tff(__expf(S[row * 260 + j] - m));
            S[row * 260 + j] = e;
            sum += e;
        }
#pragma unroll
        for (int o = 16; o; o >>= 1) sum += __shfl_xor_sync(0xffffffffu, sum, o);
        if (lane == 0) rs[row] = 1.f / sum;
    }
    __syncthreads();

    // ---- phase 3: r = exp(S) @ v, scaled by 1/rowsum ----
    float acc[2][4][4];
#pragma unroll
    for (int i = 0; i < 2; i++)
#pragma unroll
        for (int j = 0; j < 4; j++)
#pragma unroll
            for (int x = 0; x < 4; x++) acc[i][j][x] = 0.f;

    for (int sc = 0; sc < 2; sc++) {
#pragma unroll
        for (int it = 0; it < 16; it++) {
            int idx = tid + it * 256;
            int row = idx >> 5;
            int c4 = (idx & 31) << 2;
            float4 v4 = *reinterpret_cast<const float4*>(vb + (size_t)(sc * 128 + row) * SQ + c4);
            v4.x = f2tff(v4.x); v4.y = f2tff(v4.y); v4.z = f2tff(v4.z); v4.w = f2tff(v4.w);
            *reinterpret_cast<float4*>(&qs[row * 132 + c4]) = v4;
        }
        __syncthreads();
#pragma unroll
        for (int kk = 0; kk < 128; kk += 8) {
            uint32_t a[2][4];
#pragma unroll
            for (int mi = 0; mi < 2; mi++) {
                int r0 = wm * 32 + mi * 16;
                a[mi][0] = __float_as_uint(S[(r0 + gi) * 260 + sc * 128 + kk + tg]);
                a[mi][1] = __float_as_uint(S[(r0 + gi + 8) * 260 + sc * 128 + kk + tg]);
                a[mi][2] = __float_as_uint(S[(r0 + gi) * 260 + sc * 128 + kk + tg + 4]);
                a[mi][3] = __float_as_uint(S[(r0 + gi + 8) * 260 + sc * 128 + kk + tg + 4]);
            }
#pragma unroll
            for (int ni = 0; ni < 4; ni++) {
                int c0 = wn * 32 + ni * 8;
                uint32_t b0 = __float_as_uint(qs[(kk + tg) * 132 + c0 + gi]);
                uint32_t b1 = __float_as_uint(qs[(kk + tg + 4) * 132 + c0 + gi]);
                mma8(acc[0][ni], a[0], b0, b1);
                mma8(acc[1][ni], a[1], b0, b1);
            }
        }
        __syncthreads();
    }

    float* rb = r + ((size_t)b * TT + t0) * VD;
#pragma unroll
    for (int mi = 0; mi < 2; mi++)
#pragma unroll
        for (int ni = 0; ni < 4; ni++) {
            int row = wm * 32 + mi * 16 + gi;
            int col = wn * 32 + ni * 8 + tg * 2;
            float s0 = rs[row], s1 = rs[row + 8];
            rb[(size_t)row * VD + col] = acc[mi][ni][0] * s0;
            rb[(size_t)row * VD + col + 1] = acc[mi][ni][1] * s0;
            rb[(size_t)(row + 8) * VD + col] = acc[mi][ni][2] * s1;
            rb[(size_t)(row + 8) * VD + col + 1] = acc[mi][ni][3] * s1;
        }
}

// ---------------- launch ----------------
extern "C" void kernel_launch(void* const* d_in, const int* in_sizes, int n_in,
                              void* d_out, int out_size)
{
    const float* X  = (const float*)d_in[0];
    const float* Qw = (const float*)d_in[1];
    const float* Qb = (const float*)d_in[2];
    const float* Kw = (const float*)d_in[3];
    const float* Kb = (const float*)d_in[4];
    const float* Vw = (const float*)d_in[5];
    const float* Vb = (const float*)d_in[6];
    const float* W1 = (const float*)d_in[7];
    const float* b1 = (const float*)d_in[8];
    const float* W2 = (const float*)d_in[9];
    const float* b2 = (const float*)d_in[10];
    const float* W3 = (const float*)d_in[11];
    const float* b3 = (const float*)d_in[12];
    float* out = (float*)d_out;

    float *qkvp, *wp, *bp, *rp, *h1p, *h2p, *pp;
    cudaGetSymbolAddress((void**)&qkvp, g_qkv);
    cudaGetSymbolAddress((void**)&wp, g_wqkv);
    cudaGetSymbolAddress((void**)&bp, g_bqkv);
    cudaGetSymbolAddress((void**)&rp, g_r);
    cudaGetSymbolAddress((void**)&h1p, g_h1);
    cudaGetSymbolAddress((void**)&h2p, g_h2);
    cudaGetSymbolAddress((void**)&pp, g_part);

    cudaFuncSetAttribute(attn_kernel, cudaFuncAttributeMaxDynamicSharedMemorySize,
                         ATTN_SMEM_BYTES);
    cudaFuncSetAttribute(gemm_tf32_pipe, cudaFuncAttributeMaxDynamicSharedMemorySize,
                         GEMM_SMEM);

    // pack fused QKV weight + bias
    pack_qkv_kernel<<<(ND * SQ + 255) / 256, 256>>>(Qw, Kw, Vw, Qb, Kb, Vb, wp, bp);

    // fused QKV projection: [32768,128] @ [128,384] + bias, output stride 384
    gemm_tf32_pipe<<<dim3(3, 256, 1), 128, GEMM_SMEM>>>(X, wp, qkvp, bp, BB * TT, SQ, ND, 0);

    // attention
    attn_kernel<<<dim3(4, 128), 256, ATTN_SMEM_BYTES>>>(qkvp, rp);

    // MLP layer 1: [128, 32768] @ [32768, 2048], split-K 32 + sigmoid reduce
    gemm_tf32_pipe<<<dim3(FD / 128, 1, 32), 128, GEMM_SMEM>>>(rp, W1, pp, nullptr, BB, FD, TT * VD, 0);
    reduce_kernel<<<(BB * FD + 255) / 256, 256>>>(pp, b1, h1p, BB * FD, FD, 32, 1);

    // MLP layer 2: [128, 2048] @ [2048, 2048], split-K 16 + sigmoid reduce
    gemm_tf32_pipe<<<dim3(FD / 128, 1, 16), 128, GEMM_SMEM>>>(h1p, W2, pp, nullptr, BB, FD, FD, 0);
    reduce_kernel<<<(BB * FD + 255) / 256, 256>>>(pp, b2, h2p, BB * FD, FD, 16, 1);

    // MLP layer 3: [128, 2048] @ [2048, 4096], split-K 8 + bias (no act) -> out
    gemm_tf32_pipe<<<dim3(OD / 128, 1, 8), 128, GEMM_SMEM>>>(h2p, W3, pp, nullptr, BB, OD, FD, 0);
    reduce_kernel<<<(BB * OD + 255) / 256, 256>>>(pp, b3, out, BB * OD, OD, 8, 0);
}